// round 5
// baseline (speedup 1.0000x reference)
#include <cuda_runtime.h>

// AEV computer (ANI-style): radial + angular symmetry functions.
// Shapes fixed by the reference setup: B=8, A=48, S=4, NR=16 ShfR, NA=4 ShfA,
// NZ=8 ShfZ, npairs=10. Rcr=5.2, Rca=3.5. Output: (8,48,384) float32.

#define B_   8
#define A_   48
#define S_   4
#define NR   16
#define NA   4
#define NZ   8
#define NP   10            // S*(S+1)/2
#define RAD  (S_*NR)       // 64
#define ANG  (NP*NA*NZ)    // 320
#define OUTL (RAD+ANG)     // 384
#define RCR  5.2f
#define RCA  3.5f
#define PI_F 3.14159265358979323846f
#define NTHREADS 128
#define MAXP (A_*(A_-1)/2) // 1128 unordered pairs max

__global__ __launch_bounds__(NTHREADS) void aev_kernel(
    const int*   __restrict__ species,   // (B,A)
    const float* __restrict__ coords,    // (B,A,3)
    const float* __restrict__ gEtaR,     // (1)
    const float* __restrict__ gShfR,     // (16)
    const float* __restrict__ gEtaA,     // (1)
    const float* __restrict__ gZeta,     // (1)
    const float* __restrict__ gShfA,     // (4)
    const float* __restrict__ gShfZ,     // (8)
    float*       __restrict__ out)       // (B,A,384)
{
    __shared__ float sxc[A_], syc[A_], szc[A_];
    __shared__ int   ssp[A_];
    __shared__ float vx[A_], vy[A_], vz[A_];   // vec[j] = c_i - c_j
    __shared__ float sd[A_], sfca[A_];
    __shared__ alignas(16) float acc[OUTL];
    __shared__ float shR[NR], shA[NA], cZ[NZ], sZ[NZ];
    __shared__ float etaR, etaA, zeta;
    __shared__ int   nbr[A_];
    __shared__ int   wcnt[2];
    __shared__ int   ncnt;
    // per-pair precomputed angular data
    __shared__ float pca[MAXP], psa[MAXP];       // cos(theta), sin(theta)
    __shared__ float pg[NA][MAXP];               // 2*fca_j*fca_k*f2[a]
    __shared__ int   pbase[MAXP];                // acc base offset

    const int tid = threadIdx.x;
    const int bi  = blockIdx.x;      // b*A + i
    const int b   = bi / A_;
    const int i   = bi % A_;

    // ---- loads ----
    if (tid < A_) {
        int g = b * A_ + tid;
        sxc[tid] = coords[g*3 + 0];
        syc[tid] = coords[g*3 + 1];
        szc[tid] = coords[g*3 + 2];
        ssp[tid] = species[g];
    }
    if (tid < NR) shR[tid] = gShfR[tid];
    if (tid < NA) shA[tid] = gShfA[tid];
    if (tid < NZ) { float v = gShfZ[tid]; cZ[tid] = cosf(v); sZ[tid] = sinf(v); }
    if (tid == 0) { etaR = gEtaR[0]; etaA = gEtaA[0]; zeta = gZeta[0]; }
    for (int o = tid; o < OUTL; o += NTHREADS) acc[o] = 0.0f;
    __syncthreads();

    const int vi = (ssp[i] >= 0);

    // ---- Stage A: per-neighbor distances, cutoffs, radial scatter ----
    bool     inA = false;
    unsigned bal = 0;
    if (tid < 64) {
        const int j = tid;
        float fca = 0.0f;
        if (j < A_) {
            float dx = sxc[i] - sxc[j];
            float dy = syc[i] - syc[j];
            float dz = szc[i] - szc[j];
            float d2 = dx*dx + dy*dy + dz*dz;
            float d  = (j == i) ? 1.0f : sqrtf(d2);
            vx[j] = dx; vy[j] = dy; vz[j] = dz; sd[j] = d;

            const int pairok = vi && (ssp[j] >= 0) && (j != i);

            if (pairok && d <= RCA) fca = 0.5f * __cosf(d * (PI_F / RCA)) + 0.5f;
            sfca[j] = fca;

            if (pairok && d <= RCR) {
                float fc = 0.5f * __cosf(d * (PI_F / RCR)) + 0.5f;
                float w  = 0.25f * fc;
                int sbase = ssp[j] * NR;
                float lEtaR = etaR;
                #pragma unroll
                for (int r = 0; r < NR; r++) {
                    float t = d - shR[r];
                    atomicAdd(&acc[sbase + r], w * __expf(-lEtaR * t * t));
                }
            }
        }
        inA = (fca > 0.0f);
        bal = __ballot_sync(0xFFFFFFFFu, inA);
        if ((tid & 31) == 0) wcnt[tid >> 5] = __popc(bal);
    }
    __syncthreads();

    // deterministic compaction: nbr[] in ascending j order
    if (inA) {
        int base = (tid >= 32) ? wcnt[0] : 0;
        nbr[base + __popc(bal & ((1u << (tid & 31)) - 1u))] = tid;
    }
    if (tid == 0) ncnt = wcnt[0] + wcnt[1];
    __syncthreads();

    // ---- Stage B: per unordered pair (u<v), z-invariant precompute.
    //      Ordered-pair reference sum = 2x unordered; reference's 2.0 factor
    //      and 0.5 einsum prefactor cancel for the ordered sum -> weight 2.0. ----
    const int   m     = ncnt;
    const int   npair = m * (m - 1) / 2;
    const float lEtaA = etaA;

    for (int p = tid; p < npair; p += NTHREADS) {
        // triangular decode: p = v*(v-1)/2 + u, 0 <= u < v < m
        int v = (int)((sqrtf(8.0f * (float)p + 1.0f) + 1.0f) * 0.5f);
        while (v * (v - 1) / 2 > p) v--;
        while ((v + 1) * v / 2 <= p) v++;
        int u = p - v * (v - 1) / 2;
        const int jj = nbr[u], kk = nbr[v];

        float dot = vx[jj]*vx[kk] + vy[jj]*vy[kk] + vz[jj]*vz[kk];
        float dd  = sd[jj] * sd[kk];
        float ca  = 0.95f * dot / fmaxf(dd, 1e-8f);
        float sa  = sqrtf(fmaxf(1.0f - ca*ca, 0.0f));   // sin(theta), theta in [0,pi]
        pca[p] = ca; psa[p] = sa;

        float wb = 2.0f * sfca[jj] * sfca[kk];
        float ds = 0.5f * (sd[jj] + sd[kk]);
        #pragma unroll
        for (int a = 0; a < NA; a++) {
            float t = ds - shA[a];
            pg[a][p] = wb * __expf(-lEtaA * t * t);
        }

        int s1 = ssp[jj], s2 = ssp[kk];
        int lo = min(s1, s2), hi = max(s1, s2);
        int pidx = lo * (2*S_ - lo + 1) / 2 + (hi - lo);
        pbase[p] = RAD + pidx * (NA*NZ);
    }
    __syncthreads();

    // ---- Stage C: per (pair, z) item — pure FMA + shared atomics ----
    const float lzeta = zeta;
    const bool  z32   = (lzeta == 32.0f);
    const int   items = npair * NZ;

    for (int it = tid; it < items; it += NTHREADS) {
        const int z = it & (NZ - 1);
        const int p = it >> 3;

        float cth = pca[p] * cZ[z] + psa[p] * sZ[z];    // cos(theta - ShfZ[z])
        float basev = 0.5f * (1.0f + cth);
        float f1;
        if (z32) { float t = basev*basev; t = t*t; t = t*t; t = t*t; f1 = t*t; }
        else      f1 = __powf(basev, lzeta);

        int abase = pbase[p] + z;
        #pragma unroll
        for (int a = 0; a < NA; a++)
            atomicAdd(&acc[abase + a*NZ], f1 * pg[a][p]);
    }
    __syncthreads();

    // ---- write out (vectorized: 384 floats = 96 float4) ----
    float4* op4 = reinterpret_cast<float4*>(out + (size_t)bi * OUTL);
    const float4* ac4 = reinterpret_cast<const float4*>(acc);
    for (int o = tid; o < OUTL/4; o += NTHREADS) op4[o] = ac4[o];
}

extern "C" void kernel_launch(void* const* d_in, const int* in_sizes, int n_in,
                              void* d_out, int out_size) {
    const int*   species = (const int*)  d_in[0];
    const float* coords  = (const float*)d_in[1];
    const float* EtaR    = (const float*)d_in[2];
    const float* ShfR    = (const float*)d_in[3];
    const float* EtaA    = (const float*)d_in[4];
    const float* Zeta    = (const float*)d_in[5];
    const float* ShfA    = (const float*)d_in[6];
    const float* ShfZ    = (const float*)d_in[7];
    float* out = (float*)d_out;
    (void)in_sizes; (void)n_in; (void)out_size;

    aev_kernel<<<B_ * A_, NTHREADS>>>(species, coords, EtaR, ShfR, EtaA, Zeta,
                                      ShfA, ShfZ, out);
}